// round 8
// baseline (speedup 1.0000x reference)
#include <cuda_runtime.h>
#include <cuda_bf16.h>
#include <cstdint>

// MetaDynamics via mma.sync bf16 tensor cores (compute_100-safe).
// e[p,h] = A_h + sum_{k<16} M[h,k] * X[k,p];  K=16 (8 b*x + 8 c*x^2), bias in epilogue.
//   iv = -0.5*log2e/wdt^2; b = -2*iv*cen; c = iv; A = sum iv*cen^2 + log2(hgt)
//   out[p] = sum_h 2^(e[p,h])
// bf16 hi/lo split: 3 MMAs per C tile (Xhi*Mhi + Xhi*Mlo + Xlo*Mhi), K=16 each.
// M row: 32 bf16 = 64 B: [0,8)=b hi, [8,16)=c hi, [16,24)=b lo, [24,32)=c lo.
//
// R7: statically balanced persistent CTAs. 296 CTAs (2/SM on 148 SMs); work =
// 4096 units (32 point-tiles x 128 hill-chunks of 128 hills); CTA c handles the
// contiguous range [c*4096/296, (c+1)*4096/296) -> 13/14 units each (98.6% balance),
// A-fragments stay in registers across units of the same ptile.
// Also: vectorized pre_hills; per-unit partials g_part[p][chunk] + final reduce.

#define N_HILLS   16384
#define N_POINTS  4096
#define N_CV      8

#define CHUNK     128                           // hills per unit
#define NCHUNKS   (N_HILLS / CHUNK)             // 128
#define NPTILES   (N_POINTS / 128)              // 32
#define UNITS     (NPTILES * NCHUNKS)           // 4096
#define NCTAS     296

#define PITCH     80                            // 64B row + 16B pad (conflict-free LDSM)
#define BUF_DATA  (CHUNK * PITCH)               // 10240
#define BUF_A     (CHUNK * 4)                   // 512
#define BUF_BYTES (BUF_DATA + BUF_A)            // 10752

// ---- device-global scratch ----
__device__ __align__(16) __nv_bfloat16 g_M[N_HILLS * 32];       // 1 MB
__device__ __align__(16) float g_A[N_HILLS];                    // 64 KB
__device__ __align__(16) float g_part[N_POINTS * NCHUNKS];      // 2 MB  [p][chunk]

// ---- helpers ----
__device__ __forceinline__ uint32_t smem_u32(const void* p) {
    uint32_t a;
    asm("{ .reg .u64 t; cvta.to.shared.u64 t, %1; cvt.u32.u64 %0, t; }" : "=r"(a) : "l"(p));
    return a;
}
__device__ __forceinline__ float ex2f(float x) {
    float y; asm("ex2.approx.f32 %0, %1;" : "=f"(y) : "f"(x)); return y;
}
__device__ __forceinline__ void cp16(uint32_t dst, const void* src) {
    asm volatile("cp.async.cg.shared.global [%0], [%1], 16;" :: "r"(dst), "l"(src));
}
__device__ __forceinline__ void cp_commit() { asm volatile("cp.async.commit_group;" ::: "memory"); }
__device__ __forceinline__ void cp_wait1()  { asm volatile("cp.async.wait_group 1;" ::: "memory"); }
__device__ __forceinline__ void cp_wait0()  { asm volatile("cp.async.wait_group 0;" ::: "memory"); }

#define LDSM4(r, addr) \
    asm volatile("ldmatrix.sync.aligned.m8n8.x4.shared.b16 {%0,%1,%2,%3}, [%4];" \
        : "=r"((r)[0]), "=r"((r)[1]), "=r"((r)[2]), "=r"((r)[3]) : "r"(addr))

__device__ __forceinline__ void mma_acc(float c[4], const uint32_t a[4],
                                        uint32_t b0, uint32_t b1) {
    asm volatile(
        "mma.sync.aligned.m16n8k16.row.col.f32.bf16.bf16.f32 "
        "{%0,%1,%2,%3}, {%4,%5,%6,%7}, {%8,%9}, {%0,%1,%2,%3};"
        : "+f"(c[0]), "+f"(c[1]), "+f"(c[2]), "+f"(c[3])
        : "r"(a[0]), "r"(a[1]), "r"(a[2]), "r"(a[3]), "r"(b0), "r"(b1));
}

__device__ __forceinline__ void bf16_split(float v, __nv_bfloat16& hi, __nv_bfloat16& lo) {
    hi = __float2bfloat16_rn(v);
    lo = __float2bfloat16_rn(v - __bfloat162float(hi));
}
__device__ __forceinline__ uint32_t pack_bf(__nv_bfloat16 e0, __nv_bfloat16 e1) {
    uint32_t l = __bfloat16_as_ushort(e0), h = __bfloat16_as_ushort(e1);
    return l | (h << 16);
}

// ===== precompute: hill matrix M [16384][32] + bias A [16384], vectorized =====
__global__ void __launch_bounds__(256)
pre_hills(const float* __restrict__ cen,
          const float* __restrict__ wdt,
          const float* __restrict__ hgt)
{
    const int h = blockIdx.x * 256 + threadIdx.x;
    const float NEG_HALF_LOG2E = -0.72134752044448170f;
    float4 c0 = *(const float4*)(cen + h * N_CV);
    float4 c1 = *(const float4*)(cen + h * N_CV + 4);
    float4 w0 = *(const float4*)(wdt + h * N_CV);
    float4 w1 = *(const float4*)(wdt + h * N_CV + 4);
    float cv[8] = {c0.x, c0.y, c0.z, c0.w, c1.x, c1.y, c1.z, c1.w};
    float wv[8] = {w0.x, w0.y, w0.z, w0.w, w1.x, w1.y, w1.z, w1.w};

    float A = log2f(hgt[h]);
    __nv_bfloat16 bh[8], bl[8], ch_[8], cl[8];
    #pragma unroll
    for (int d = 0; d < N_CV; ++d) {
        float iv = NEG_HALF_LOG2E / (wv[d] * wv[d]);
        float b  = -2.0f * iv * cv[d];
        A = fmaf(iv * cv[d], cv[d], A);
        bf16_split(b, bh[d], bl[d]);
        bf16_split(iv, ch_[d], cl[d]);
    }
    uint4 o0, o1, o2, o3;
    o0.x = pack_bf(bh[0], bh[1]);  o0.y = pack_bf(bh[2], bh[3]);
    o0.z = pack_bf(bh[4], bh[5]);  o0.w = pack_bf(bh[6], bh[7]);
    o1.x = pack_bf(ch_[0], ch_[1]); o1.y = pack_bf(ch_[2], ch_[3]);
    o1.z = pack_bf(ch_[4], ch_[5]); o1.w = pack_bf(ch_[6], ch_[7]);
    o2.x = pack_bf(bl[0], bl[1]);  o2.y = pack_bf(bl[2], bl[3]);
    o2.z = pack_bf(bl[4], bl[5]);  o2.w = pack_bf(bl[6], bl[7]);
    o3.x = pack_bf(cl[0], cl[1]);  o3.y = pack_bf(cl[2], cl[3]);
    o3.z = pack_bf(cl[4], cl[5]);  o3.w = pack_bf(cl[6], cl[7]);
    uint4* dst = (uint4*)(g_M + h * 32);
    dst[0] = o0; dst[1] = o1; dst[2] = o2; dst[3] = o3;
    g_A[h] = A;
}

// ===== main tensor-core kernel (persistent, balanced ranges) =====
__device__ __forceinline__ void copy_chunk(uint32_t bufaddr, int hbase, int tid)
{
    const char* src = (const char*)g_M + (size_t)hbase * 64;
    #pragma unroll
    for (int k = 0; k < 2; ++k) {
        const int idx = tid + k * 256;
        const int row = idx >> 2;
        const int c   = idx & 3;
        cp16(bufaddr + row * PITCH + c * 16, src + row * 64 + c * 16);
    }
    if (tid < 32)
        cp16(bufaddr + BUF_DATA + tid * 16, (const char*)(g_A + hbase) + tid * 16);
}

__device__ __forceinline__ void build_A_frags(const float* __restrict__ col,
                                              int p0w, int g, int q,
                                              uint32_t Ahi[4], uint32_t Alo[4])
{
    const int rlo = p0w + g, rhi = rlo + 8;
    float2 xa = *(const float2*)(col + rlo * N_CV + 2 * q);
    float2 xb = *(const float2*)(col + rhi * N_CV + 2 * q);
    __nv_bfloat16 h0, l0, h1, l1;
    bf16_split(xa.x, h0, l0); bf16_split(xa.y, h1, l1);
    Ahi[0] = pack_bf(h0, h1);  Alo[0] = pack_bf(l0, l1);
    bf16_split(xb.x, h0, l0); bf16_split(xb.y, h1, l1);
    Ahi[1] = pack_bf(h0, h1);  Alo[1] = pack_bf(l0, l1);
    bf16_split(xa.x * xa.x, h0, l0); bf16_split(xa.y * xa.y, h1, l1);
    Ahi[2] = pack_bf(h0, h1);  Alo[2] = pack_bf(l0, l1);
    bf16_split(xb.x * xb.x, h0, l0); bf16_split(xb.y * xb.y, h1, l1);
    Ahi[3] = pack_bf(h0, h1);  Alo[3] = pack_bf(l0, l1);
}

__global__ void __launch_bounds__(256, 2)
metadyn_mma(const float* __restrict__ col)
{
    __shared__ __align__(16) char sbuf[2 * BUF_BYTES];

    const int tid  = threadIdx.x;
    const int lane = tid & 31;
    const int warp = tid >> 5;
    const int q    = lane & 3;
    const int g    = lane >> 2;

    const int u0 = (int)(((long long)blockIdx.x * UNITS) / NCTAS);
    const int u1 = (int)(((long long)(blockIdx.x + 1) * UNITS) / NCTAS);

    const uint32_t sb = smem_u32(sbuf);
    const uint32_t lanebase = (uint32_t)(((lane & 7) | ((lane >> 4) << 3)) * PITCH
                                         + ((lane >> 3) & 1) * 16);

    int cur_pt = u0 >> 7;                 // ptile of first unit
    int p0w = cur_pt * 128 + warp * 16;
    uint32_t Ahi[4], Alo[4];
    build_A_frags(col, p0w, g, q, Ahi, Alo);

    copy_chunk(sb, (u0 & (NCHUNKS - 1)) * CHUNK, tid);
    cp_commit();

    for (int u = u0; u < u1; ++u) {
        const uint32_t buf = sb + (uint32_t)((u - u0) & 1) * BUF_BYTES;
        if (u + 1 < u1) {
            copy_chunk(sb + (uint32_t)((u + 1 - u0) & 1) * BUF_BYTES,
                       ((u + 1) & (NCHUNKS - 1)) * CHUNK, tid);
            cp_commit();
            cp_wait1();
        } else {
            cp_wait0();
        }
        __syncthreads();

        const int pt = u >> 7;
        if (pt != cur_pt) {
            cur_pt = pt;
            p0w = pt * 128 + warp * 16;
            build_A_frags(col, p0w, g, q, Ahi, Alo);
        }

        float acc0 = 0.f, acc1 = 0.f;
        #pragma unroll
        for (int st = 0; st < CHUNK / 16; ++st) {      // 16 hills per step
            const uint32_t base = buf + (uint32_t)st * (16 * PITCH) + lanebase;
            uint32_t bh[4], bl[4];
            LDSM4(bh, base + 0);     // M hi: {n0 b0,b1, n1 b0,b1}
            LDSM4(bl, base + 32);    // M lo

            float C0[4] = {0.f, 0.f, 0.f, 0.f};
            float C1[4] = {0.f, 0.f, 0.f, 0.f};
            mma_acc(C0, Ahi, bh[0], bh[1]);
            mma_acc(C0, Ahi, bl[0], bl[1]);
            mma_acc(C0, Alo, bh[0], bh[1]);
            mma_acc(C1, Ahi, bh[2], bh[3]);
            mma_acc(C1, Ahi, bl[2], bl[3]);
            mma_acc(C1, Alo, bh[2], bh[3]);

            // bias (fp32) + exp2; C0 cols = hills st*16 + 2q,2q+1 ; C1 cols = +8
            float2 a0 = *(const float2*)(sbuf + (buf - sb) + BUF_DATA + (st * 16 + 2 * q) * 4);
            float2 a1 = *(const float2*)(sbuf + (buf - sb) + BUF_DATA + (st * 16 + 8 + 2 * q) * 4);
            acc0 += ex2f(C0[0] + a0.x) + ex2f(C0[1] + a0.y)
                  + ex2f(C1[0] + a1.x) + ex2f(C1[1] + a1.y);
            acc1 += ex2f(C0[2] + a0.x) + ex2f(C0[3] + a0.y)
                  + ex2f(C1[2] + a1.x) + ex2f(C1[3] + a1.y);
        }

        // flush this unit: quad-reduce, write partials [p][chunk]
        acc0 += __shfl_xor_sync(0xFFFFFFFFu, acc0, 1);
        acc0 += __shfl_xor_sync(0xFFFFFFFFu, acc0, 2);
        acc1 += __shfl_xor_sync(0xFFFFFFFFu, acc1, 1);
        acc1 += __shfl_xor_sync(0xFFFFFFFFu, acc1, 2);
        if (q == 0) {
            const int chnk = u & (NCHUNKS - 1);
            g_part[(p0w + g) * NCHUNKS + chnk]     = acc0;
            g_part[(p0w + g + 8) * NCHUNKS + chnk] = acc1;
        }
        __syncthreads();
    }
}

// ===== final reduce over 128 chunks per point =====
__global__ void __launch_bounds__(256)
metadyn_reduce(float* __restrict__ out)
{
    const int p = blockIdx.x * 256 + threadIdx.x;
    const float4* v = (const float4*)(g_part + p * NCHUNKS);
    float4 s0 = make_float4(0.f,0.f,0.f,0.f), s1 = s0, s2 = s0, s3 = s0;
    #pragma unroll
    for (int i = 0; i < NCHUNKS / 16; ++i) {
        float4 a = v[4*i], b = v[4*i+1], c = v[4*i+2], d = v[4*i+3];
        s0.x += a.x; s0.y += a.y; s0.z += a.z; s0.w += a.w;
        s1.x += b.x; s1.y += b.y; s1.z += b.z; s1.w += b.w;
        s2.x += c.x; s2.y += c.y; s2.z += c.z; s2.w += c.w;
        s3.x += d.x; s3.y += d.y; s3.z += d.z; s3.w += d.w;
    }
    float r = ((s0.x + s0.y) + (s0.z + s0.w)) + ((s1.x + s1.y) + (s1.z + s1.w))
            + ((s2.x + s2.y) + (s2.z + s2.w)) + ((s3.x + s3.y) + (s3.z + s3.w));
    out[p] = r;
}

extern "C" void kernel_launch(void* const* d_in, const int* in_sizes, int n_in,
                              void* d_out, int out_size)
{
    const float* col = (const float*)d_in[0];
    const float* cen = (const float*)d_in[1];
    const float* wdt = (const float*)d_in[2];
    const float* hgt = (const float*)d_in[3];
    float* out = (float*)d_out;

    pre_hills<<<N_HILLS / 256, 256>>>(cen, wdt, hgt);
    metadyn_mma<<<NCTAS, 256>>>(col);
    metadyn_reduce<<<N_POINTS / 256, 256>>>(out);
}

// round 9
// speedup vs baseline: 1.0008x; 1.0008x over previous
#include <cuda_runtime.h>
#include <cuda_bf16.h>
#include <cstdint>

// MetaDynamics via mma.sync bf16 tensor cores (compute_100-safe).
// e[p,h] = A_h + sum_{k<16} M[h,k] * X[k,p];  K=16 (8 b*x + 8 c*x^2), bias in epilogue.
//   iv = -0.5*log2e/wdt^2; b = -2*iv*cen; c = iv; A = sum iv*cen^2 + log2(hgt)
//   out[p] = sum_h 2^(e[p,h])
// bf16 hi/lo split: 3 MMAs per C tile (Xhi*Mhi + Xhi*Mlo + Xlo*Mhi), K=16 each.
//
// R9: FUSED conversion (no pre_hills kernel, no cp.async). Chunk-major persistent:
// 296 CTAs over 4096 units (u = chunk*32 + ptile); contiguous ranges span 1-2 chunks.
// On chunk entry the CTA converts its 128 hills straight into the LDSM smem layout
// (threads 0-127, one hill each). Units within a chunk need no __syncthreads
// (smem read-only; A-fragments rebuilt per unit from L1-hot col).
// Partials g_part[p][chunk]; small reduce kernel. 2 launches total.

#define N_HILLS   16384
#define N_POINTS  4096
#define N_CV      8

#define CHUNK     128                           // hills per chunk
#define NCHUNKS   (N_HILLS / CHUNK)             // 128
#define NPTILES   (N_POINTS / 128)              // 32
#define UNITS     (NPTILES * NCHUNKS)           // 4096
#define NCTAS     296

#define PITCH     80                            // 64B row + 16B pad (conflict-free LDSM)
#define BUF_DATA  (CHUNK * PITCH)               // 10240
#define BUF_BYTES (BUF_DATA + CHUNK * 4)        // + 512 fp32 bias

// ---- device-global scratch ----
__device__ __align__(16) float g_part[N_POINTS * NCHUNKS];      // 2 MB  [p][chunk]

// ---- helpers ----
__device__ __forceinline__ uint32_t smem_u32(const void* p) {
    uint32_t a;
    asm("{ .reg .u64 t; cvta.to.shared.u64 t, %1; cvt.u32.u64 %0, t; }" : "=r"(a) : "l"(p));
    return a;
}
__device__ __forceinline__ float ex2f(float x) {
    float y; asm("ex2.approx.f32 %0, %1;" : "=f"(y) : "f"(x)); return y;
}

#define LDSM4(r, addr) \
    asm volatile("ldmatrix.sync.aligned.m8n8.x4.shared.b16 {%0,%1,%2,%3}, [%4];" \
        : "=r"((r)[0]), "=r"((r)[1]), "=r"((r)[2]), "=r"((r)[3]) : "r"(addr))

__device__ __forceinline__ void mma_acc(float c[4], const uint32_t a[4],
                                        uint32_t b0, uint32_t b1) {
    asm volatile(
        "mma.sync.aligned.m16n8k16.row.col.f32.bf16.bf16.f32 "
        "{%0,%1,%2,%3}, {%4,%5,%6,%7}, {%8,%9}, {%0,%1,%2,%3};"
        : "+f"(c[0]), "+f"(c[1]), "+f"(c[2]), "+f"(c[3])
        : "r"(a[0]), "r"(a[1]), "r"(a[2]), "r"(a[3]), "r"(b0), "r"(b1));
}

__device__ __forceinline__ void bf16_split(float v, __nv_bfloat16& hi, __nv_bfloat16& lo) {
    hi = __float2bfloat16_rn(v);
    lo = __float2bfloat16_rn(v - __bfloat162float(hi));
}
__device__ __forceinline__ uint32_t pack_bf(__nv_bfloat16 e0, __nv_bfloat16 e1) {
    uint32_t l = __bfloat16_as_ushort(e0), h = __bfloat16_as_ushort(e1);
    return l | (h << 16);
}

__device__ __forceinline__ void build_A_frags(const float* __restrict__ col,
                                              int p0w, int g, int q,
                                              uint32_t Ahi[4], uint32_t Alo[4])
{
    const int rlo = p0w + g, rhi = rlo + 8;
    float2 xa = *(const float2*)(col + rlo * N_CV + 2 * q);
    float2 xb = *(const float2*)(col + rhi * N_CV + 2 * q);
    __nv_bfloat16 h0, l0, h1, l1;
    bf16_split(xa.x, h0, l0); bf16_split(xa.y, h1, l1);
    Ahi[0] = pack_bf(h0, h1);  Alo[0] = pack_bf(l0, l1);
    bf16_split(xb.x, h0, l0); bf16_split(xb.y, h1, l1);
    Ahi[1] = pack_bf(h0, h1);  Alo[1] = pack_bf(l0, l1);
    bf16_split(xa.x * xa.x, h0, l0); bf16_split(xa.y * xa.y, h1, l1);
    Ahi[2] = pack_bf(h0, h1);  Alo[2] = pack_bf(l0, l1);
    bf16_split(xb.x * xb.x, h0, l0); bf16_split(xb.y * xb.y, h1, l1);
    Ahi[3] = pack_bf(h0, h1);  Alo[3] = pack_bf(l0, l1);
}

// Convert 128 hills of chunk `chnk` into smem LDSM layout + fp32 bias.
// Row r bytes: [0,16)=b hi, [16,32)=c hi, [32,48)=b lo, [48,64)=c lo at r*PITCH.
__device__ __forceinline__ void convert_chunk(char* sbuf, int chnk, int tid,
                                              const float* __restrict__ cen,
                                              const float* __restrict__ wdt,
                                              const float* __restrict__ hgt)
{
    if (tid >= CHUNK) return;
    const int h = chnk * CHUNK + tid;
    const float NEG_HALF_LOG2E = -0.72134752044448170f;
    float4 c0 = *(const float4*)(cen + h * N_CV);
    float4 c1 = *(const float4*)(cen + h * N_CV + 4);
    float4 w0 = *(const float4*)(wdt + h * N_CV);
    float4 w1 = *(const float4*)(wdt + h * N_CV + 4);
    float cv[8] = {c0.x, c0.y, c0.z, c0.w, c1.x, c1.y, c1.z, c1.w};
    float wv[8] = {w0.x, w0.y, w0.z, w0.w, w1.x, w1.y, w1.z, w1.w};

    float A = log2f(hgt[h]);
    __nv_bfloat16 bh[8], bl[8], ch_[8], cl[8];
    #pragma unroll
    for (int d = 0; d < N_CV; ++d) {
        float iv = NEG_HALF_LOG2E / (wv[d] * wv[d]);
        float b  = -2.0f * iv * cv[d];
        A = fmaf(iv * cv[d], cv[d], A);
        bf16_split(b, bh[d], bl[d]);
        bf16_split(iv, ch_[d], cl[d]);
    }
    uint4 o0, o1, o2, o3;
    o0.x = pack_bf(bh[0], bh[1]);   o0.y = pack_bf(bh[2], bh[3]);
    o0.z = pack_bf(bh[4], bh[5]);   o0.w = pack_bf(bh[6], bh[7]);
    o1.x = pack_bf(ch_[0], ch_[1]); o1.y = pack_bf(ch_[2], ch_[3]);
    o1.z = pack_bf(ch_[4], ch_[5]); o1.w = pack_bf(ch_[6], ch_[7]);
    o2.x = pack_bf(bl[0], bl[1]);   o2.y = pack_bf(bl[2], bl[3]);
    o2.z = pack_bf(bl[4], bl[5]);   o2.w = pack_bf(bl[6], bl[7]);
    o3.x = pack_bf(cl[0], cl[1]);   o3.y = pack_bf(cl[2], cl[3]);
    o3.z = pack_bf(cl[4], cl[5]);   o3.w = pack_bf(cl[6], cl[7]);
    char* row = sbuf + tid * PITCH;
    *(uint4*)(row + 0)  = o0;
    *(uint4*)(row + 16) = o1;
    *(uint4*)(row + 32) = o2;
    *(uint4*)(row + 48) = o3;
    *(float*)(sbuf + BUF_DATA + tid * 4) = A;
}

__global__ void __launch_bounds__(256, 2)
metadyn_fused(const float* __restrict__ col,
              const float* __restrict__ cen,
              const float* __restrict__ wdt,
              const float* __restrict__ hgt)
{
    __shared__ __align__(16) char sbuf[BUF_BYTES];

    const int tid  = threadIdx.x;
    const int lane = tid & 31;
    const int warp = tid >> 5;
    const int q    = lane & 3;
    const int g    = lane >> 2;

    const int u0 = (int)(((long long)blockIdx.x * UNITS) / NCTAS);
    const int u1 = (int)(((long long)(blockIdx.x + 1) * UNITS) / NCTAS);

    const uint32_t sb = smem_u32(sbuf);
    // ldmatrix x4: lanes 0-7 rows 0-7 @+0, 8-15 rows 0-7 @+16, 16-23 rows 8-15 @+0, 24-31 @+16
    const uint32_t lanebase = (uint32_t)(((lane & 7) | ((lane >> 4) << 3)) * PITCH
                                         + ((lane >> 3) & 1) * 16);

    int cur_chunk = -1;

    for (int u = u0; u < u1; ++u) {
        const int chnk = u >> 5;           // unit = chunk*32 + ptile
        const int pt   = u & 31;

        if (chnk != cur_chunk) {
            if (cur_chunk >= 0) __syncthreads();   // all warps done reading old chunk
            convert_chunk(sbuf, chnk, tid, cen, wdt, hgt);
            __syncthreads();                       // conversion visible
            cur_chunk = chnk;
        }

        const int p0w = pt * 128 + warp * 16;
        uint32_t Ahi[4], Alo[4];
        build_A_frags(col, p0w, g, q, Ahi, Alo);

        float acc0 = 0.f, acc1 = 0.f;
        #pragma unroll
        for (int st = 0; st < CHUNK / 16; ++st) {      // 16 hills per step
            const uint32_t base = sb + (uint32_t)st * (16 * PITCH) + lanebase;
            uint32_t bh[4], bl[4];
            LDSM4(bh, base + 0);     // M hi: {n0 b0,b1, n1 b0,b1}
            LDSM4(bl, base + 32);    // M lo

            float C0[4] = {0.f, 0.f, 0.f, 0.f};
            float C1[4] = {0.f, 0.f, 0.f, 0.f};
            mma_acc(C0, Ahi, bh[0], bh[1]);
            mma_acc(C0, Ahi, bl[0], bl[1]);
            mma_acc(C0, Alo, bh[0], bh[1]);
            mma_acc(C1, Ahi, bh[2], bh[3]);
            mma_acc(C1, Ahi, bl[2], bl[3]);
            mma_acc(C1, Alo, bh[2], bh[3]);

            // bias (fp32) + exp2; C0 cols = hills st*16 + 2q,2q+1 ; C1 cols = +8
            float2 a0 = *(const float2*)(sbuf + BUF_DATA + (st * 16 + 2 * q) * 4);
            float2 a1 = *(const float2*)(sbuf + BUF_DATA + (st * 16 + 8 + 2 * q) * 4);
            acc0 += ex2f(C0[0] + a0.x) + ex2f(C0[1] + a0.y)
                  + ex2f(C1[0] + a1.x) + ex2f(C1[1] + a1.y);
            acc1 += ex2f(C0[2] + a0.x) + ex2f(C0[3] + a0.y)
                  + ex2f(C1[2] + a1.x) + ex2f(C1[3] + a1.y);
        }

        // flush this unit: quad-reduce, write partials [p][chunk]
        acc0 += __shfl_xor_sync(0xFFFFFFFFu, acc0, 1);
        acc0 += __shfl_xor_sync(0xFFFFFFFFu, acc0, 2);
        acc1 += __shfl_xor_sync(0xFFFFFFFFu, acc1, 1);
        acc1 += __shfl_xor_sync(0xFFFFFFFFu, acc1, 2);
        if (q == 0) {
            g_part[(p0w + g) * NCHUNKS + chnk]     = acc0;
            g_part[(p0w + g + 8) * NCHUNKS + chnk] = acc1;
        }
    }
}

// ===== final reduce over 128 chunks per point =====
__global__ void __launch_bounds__(256)
metadyn_reduce(float* __restrict__ out)
{
    const int p = blockIdx.x * 256 + threadIdx.x;
    const float4* v = (const float4*)(g_part + p * NCHUNKS);
    float4 s0 = make_float4(0.f,0.f,0.f,0.f), s1 = s0, s2 = s0, s3 = s0;
    #pragma unroll
    for (int i = 0; i < NCHUNKS / 16; ++i) {
        float4 a = v[4*i], b = v[4*i+1], c = v[4*i+2], d = v[4*i+3];
        s0.x += a.x; s0.y += a.y; s0.z += a.z; s0.w += a.w;
        s1.x += b.x; s1.y += b.y; s1.z += b.z; s1.w += b.w;
        s2.x += c.x; s2.y += c.y; s2.z += c.z; s2.w += c.w;
        s3.x += d.x; s3.y += d.y; s3.z += d.z; s3.w += d.w;
    }
    float r = ((s0.x + s0.y) + (s0.z + s0.w)) + ((s1.x + s1.y) + (s1.z + s1.w))
            + ((s2.x + s2.y) + (s2.z + s2.w)) + ((s3.x + s3.y) + (s3.z + s3.w));
    out[p] = r;
}

extern "C" void kernel_launch(void* const* d_in, const int* in_sizes, int n_in,
                              void* d_out, int out_size)
{
    const float* col = (const float*)d_in[0];
    const float* cen = (const float*)d_in[1];
    const float* wdt = (const float*)d_in[2];
    const float* hgt = (const float*)d_in[3];
    float* out = (float*)d_out;

    metadyn_fused<<<NCTAS, 256>>>(col, cen, wdt, hgt);
    metadyn_reduce<<<N_POINTS / 256, 256>>>(out);
}

// round 11
// speedup vs baseline: 1.0859x; 1.0850x over previous
#include <cuda_runtime.h>
#include <cuda_bf16.h>
#include <cstdint>

// MetaDynamics via mma.sync bf16 tensor cores (compute_100-safe).
// e[p,h] = A_h + sum_{k<16} M[h,k] * X[k,p];  K=16 (8 b*x + 8 c*x^2), bias in epilogue.
//   iv = -0.5*log2e/wdt^2; b = -2*iv*cen; c = iv; A = sum iv*cen^2 + log2(hgt)
//   out[p] = sum_h 2^(e[p,h])
// bf16 hi/lo split: 3 MMAs per C tile (Xhi*Mhi + Xhi*Mlo + Xlo*Mhi), K=16 each.
// M row: 32 bf16 = 64 B: [0,8)=b hi, [8,16)=c hi, [16,24)=b lo, [24,32)=c lo.
//
// R10 (resubmit after infra failure) = R8 main kernel (persistent balanced,
// cp.async double-buffer — measured ~25us) + register accumulation across chunks:
// CTA's contiguous units are chunks of the SAME ptile (ptile-major order), so flush
// only on ptile change -> partials shrink to [p][16 slots] (256 KB), reduce reads
// 16 floats/point (~1us, was 8.8us). pre_hills: 2 hills/thread for MLP.

#define N_HILLS   16384
#define N_POINTS  4096
#define N_CV      8

#define CHUNK     128
#define NCHUNKS   (N_HILLS / CHUNK)             // 128
#define NPTILES   (N_POINTS / 128)              // 32
#define UNITS     (NPTILES * NCHUNKS)           // 4096 (u = ptile*128 + chunk)
#define NCTAS     296
#define SLOTS     16

#define PITCH     80                            // 64B row + 16B pad (conflict-free LDSM)
#define BUF_DATA  (CHUNK * PITCH)               // 10240
#define BUF_A     (CHUNK * 4)                   // 512
#define BUF_BYTES (BUF_DATA + BUF_A)            // 10752

// ---- device-global scratch (zero-initialized at module load; unwritten slots stay 0) ----
__device__ __align__(16) __nv_bfloat16 g_M[N_HILLS * 32];       // 1 MB
__device__ __align__(16) float g_A[N_HILLS];                    // 64 KB
__device__ __align__(16) float g_part[N_POINTS * SLOTS];        // 256 KB

// ---- helpers ----
__device__ __forceinline__ uint32_t smem_u32(const void* p) {
    uint32_t a;
    asm("{ .reg .u64 t; cvta.to.shared.u64 t, %1; cvt.u32.u64 %0, t; }" : "=r"(a) : "l"(p));
    return a;
}
__device__ __forceinline__ float ex2f(float x) {
    float y; asm("ex2.approx.f32 %0, %1;" : "=f"(y) : "f"(x)); return y;
}
__device__ __forceinline__ void cp16(uint32_t dst, const void* src) {
    asm volatile("cp.async.cg.shared.global [%0], [%1], 16;" :: "r"(dst), "l"(src));
}
__device__ __forceinline__ void cp_commit() { asm volatile("cp.async.commit_group;" ::: "memory"); }
__device__ __forceinline__ void cp_wait1()  { asm volatile("cp.async.wait_group 1;" ::: "memory"); }
__device__ __forceinline__ void cp_wait0()  { asm volatile("cp.async.wait_group 0;" ::: "memory"); }

#define LDSM4(r, addr) \
    asm volatile("ldmatrix.sync.aligned.m8n8.x4.shared.b16 {%0,%1,%2,%3}, [%4];" \
        : "=r"((r)[0]), "=r"((r)[1]), "=r"((r)[2]), "=r"((r)[3]) : "r"(addr))

__device__ __forceinline__ void mma_acc(float c[4], const uint32_t a[4],
                                        uint32_t b0, uint32_t b1) {
    asm volatile(
        "mma.sync.aligned.m16n8k16.row.col.f32.bf16.bf16.f32 "
        "{%0,%1,%2,%3}, {%4,%5,%6,%7}, {%8,%9}, {%0,%1,%2,%3};"
        : "+f"(c[0]), "+f"(c[1]), "+f"(c[2]), "+f"(c[3])
        : "r"(a[0]), "r"(a[1]), "r"(a[2]), "r"(a[3]), "r"(b0), "r"(b1));
}

__device__ __forceinline__ void bf16_split(float v, __nv_bfloat16& hi, __nv_bfloat16& lo) {
    hi = __float2bfloat16_rn(v);
    lo = __float2bfloat16_rn(v - __bfloat162float(hi));
}
__device__ __forceinline__ uint32_t pack_bf(__nv_bfloat16 e0, __nv_bfloat16 e1) {
    uint32_t l = __bfloat16_as_ushort(e0), h = __bfloat16_as_ushort(e1);
    return l | (h << 16);
}

// ===== precompute: hill matrix M [16384][32] + bias A [16384]; 2 hills/thread =====
__device__ __forceinline__ void conv_hill(int h,
                                          const float* __restrict__ cen,
                                          const float* __restrict__ wdt,
                                          const float* __restrict__ hgt)
{
    const float NEG_HALF_LOG2E = -0.72134752044448170f;
    float4 c0 = *(const float4*)(cen + h * N_CV);
    float4 c1 = *(const float4*)(cen + h * N_CV + 4);
    float4 w0 = *(const float4*)(wdt + h * N_CV);
    float4 w1 = *(const float4*)(wdt + h * N_CV + 4);
    float cv[8] = {c0.x, c0.y, c0.z, c0.w, c1.x, c1.y, c1.z, c1.w};
    float wv[8] = {w0.x, w0.y, w0.z, w0.w, w1.x, w1.y, w1.z, w1.w};

    float A = log2f(hgt[h]);
    __nv_bfloat16 bh[8], bl[8], ch_[8], cl[8];
    #pragma unroll
    for (int d = 0; d < N_CV; ++d) {
        float iv = NEG_HALF_LOG2E / (wv[d] * wv[d]);
        float b  = -2.0f * iv * cv[d];
        A = fmaf(iv * cv[d], cv[d], A);
        bf16_split(b, bh[d], bl[d]);
        bf16_split(iv, ch_[d], cl[d]);
    }
    uint4 o0, o1, o2, o3;
    o0.x = pack_bf(bh[0], bh[1]);   o0.y = pack_bf(bh[2], bh[3]);
    o0.z = pack_bf(bh[4], bh[5]);   o0.w = pack_bf(bh[6], bh[7]);
    o1.x = pack_bf(ch_[0], ch_[1]); o1.y = pack_bf(ch_[2], ch_[3]);
    o1.z = pack_bf(ch_[4], ch_[5]); o1.w = pack_bf(ch_[6], ch_[7]);
    o2.x = pack_bf(bl[0], bl[1]);   o2.y = pack_bf(bl[2], bl[3]);
    o2.z = pack_bf(bl[4], bl[5]);   o2.w = pack_bf(bl[6], bl[7]);
    o3.x = pack_bf(cl[0], cl[1]);   o3.y = pack_bf(cl[2], cl[3]);
    o3.z = pack_bf(cl[4], cl[5]);   o3.w = pack_bf(cl[6], cl[7]);
    uint4* dst = (uint4*)(g_M + h * 32);
    dst[0] = o0; dst[1] = o1; dst[2] = o2; dst[3] = o3;
    g_A[h] = A;
}

__global__ void __launch_bounds__(256)
pre_hills(const float* __restrict__ cen,
          const float* __restrict__ wdt,
          const float* __restrict__ hgt)
{
    const int h = blockIdx.x * 512 + threadIdx.x;
    conv_hill(h, cen, wdt, hgt);
    conv_hill(h + 256, cen, wdt, hgt);
}

// ===== main tensor-core kernel (persistent, balanced, register-accumulated) =====
__device__ __forceinline__ void copy_chunk(uint32_t bufaddr, int hbase, int tid)
{
    const char* src = (const char*)g_M + (size_t)hbase * 64;
    #pragma unroll
    for (int k = 0; k < 2; ++k) {
        const int idx = tid + k * 256;
        const int row = idx >> 2;
        const int c   = idx & 3;
        cp16(bufaddr + row * PITCH + c * 16, src + row * 64 + c * 16);
    }
    if (tid < 32)
        cp16(bufaddr + BUF_DATA + tid * 16, (const char*)(g_A + hbase) + tid * 16);
}

__device__ __forceinline__ void build_A_frags(const float* __restrict__ col,
                                              int p0w, int g, int q,
                                              uint32_t Ahi[4], uint32_t Alo[4])
{
    const int rlo = p0w + g, rhi = rlo + 8;
    float2 xa = *(const float2*)(col + rlo * N_CV + 2 * q);
    float2 xb = *(const float2*)(col + rhi * N_CV + 2 * q);
    __nv_bfloat16 h0, l0, h1, l1;
    bf16_split(xa.x, h0, l0); bf16_split(xa.y, h1, l1);
    Ahi[0] = pack_bf(h0, h1);  Alo[0] = pack_bf(l0, l1);
    bf16_split(xb.x, h0, l0); bf16_split(xb.y, h1, l1);
    Ahi[1] = pack_bf(h0, h1);  Alo[1] = pack_bf(l0, l1);
    bf16_split(xa.x * xa.x, h0, l0); bf16_split(xa.y * xa.y, h1, l1);
    Ahi[2] = pack_bf(h0, h1);  Alo[2] = pack_bf(l0, l1);
    bf16_split(xb.x * xb.x, h0, l0); bf16_split(xb.y * xb.y, h1, l1);
    Ahi[3] = pack_bf(h0, h1);  Alo[3] = pack_bf(l0, l1);
}

__device__ __forceinline__ void flush(int pt, int p0w, int g, int q,
                                      float acc0, float acc1)
{
    // quad reduce (lanes sharing g hold disjoint hill columns)
    acc0 += __shfl_xor_sync(0xFFFFFFFFu, acc0, 1);
    acc0 += __shfl_xor_sync(0xFFFFFFFFu, acc0, 2);
    acc1 += __shfl_xor_sync(0xFFFFFFFFu, acc1, 1);
    acc1 += __shfl_xor_sync(0xFFFFFFFFu, acc1, 2);
    if (q == 0) {
        const int slot = (int)blockIdx.x - ((pt * NCTAS) >> 5);   // base = floor(pt*296/32)
        g_part[(p0w + g) * SLOTS + slot]     = acc0;
        g_part[(p0w + g + 8) * SLOTS + slot] = acc1;
    }
}

__global__ void __launch_bounds__(256, 2)
metadyn_mma(const float* __restrict__ col)
{
    __shared__ __align__(16) char sbuf[2 * BUF_BYTES];

    const int tid  = threadIdx.x;
    const int lane = tid & 31;
    const int warp = tid >> 5;
    const int q    = lane & 3;
    const int g    = lane >> 2;

    const int u0 = (int)(((long long)blockIdx.x * UNITS) / NCTAS);
    const int u1 = (int)(((long long)(blockIdx.x + 1) * UNITS) / NCTAS);

    const uint32_t sb = smem_u32(sbuf);
    const uint32_t lanebase = (uint32_t)(((lane & 7) | ((lane >> 4) << 3)) * PITCH
                                         + ((lane >> 3) & 1) * 16);

    int cur_pt = u0 >> 7;
    int p0w = cur_pt * 128 + warp * 16;
    uint32_t Ahi[4], Alo[4];
    build_A_frags(col, p0w, g, q, Ahi, Alo);

    copy_chunk(sb, (u0 & (NCHUNKS - 1)) * CHUNK, tid);
    cp_commit();

    float acc0 = 0.f, acc1 = 0.f;

    for (int u = u0; u < u1; ++u) {
        const uint32_t buf = sb + (uint32_t)((u - u0) & 1) * BUF_BYTES;
        if (u + 1 < u1) {
            copy_chunk(sb + (uint32_t)((u + 1 - u0) & 1) * BUF_BYTES,
                       ((u + 1) & (NCHUNKS - 1)) * CHUNK, tid);
            cp_commit();
            cp_wait1();
        } else {
            cp_wait0();
        }
        __syncthreads();

        const int pt = u >> 7;
        if (pt != cur_pt) {
            flush(cur_pt, p0w, g, q, acc0, acc1);
            acc0 = 0.f; acc1 = 0.f;
            cur_pt = pt;
            p0w = pt * 128 + warp * 16;
            build_A_frags(col, p0w, g, q, Ahi, Alo);
        }

        #pragma unroll
        for (int st = 0; st < CHUNK / 16; ++st) {      // 16 hills per step
            const uint32_t base = buf + (uint32_t)st * (16 * PITCH) + lanebase;
            uint32_t bh[4], bl[4];
            LDSM4(bh, base + 0);     // M hi: {n0 b0,b1, n1 b0,b1}
            LDSM4(bl, base + 32);    // M lo

            float C0[4] = {0.f, 0.f, 0.f, 0.f};
            float C1[4] = {0.f, 0.f, 0.f, 0.f};
            mma_acc(C0, Ahi, bh[0], bh[1]);
            mma_acc(C0, Ahi, bl[0], bl[1]);
            mma_acc(C0, Alo, bh[0], bh[1]);
            mma_acc(C1, Ahi, bh[2], bh[3]);
            mma_acc(C1, Ahi, bl[2], bl[3]);
            mma_acc(C1, Alo, bh[2], bh[3]);

            // bias (fp32) + exp2; C0 cols = hills st*16 + 2q,2q+1 ; C1 cols = +8
            float2 a0 = *(const float2*)(sbuf + (buf - sb) + BUF_DATA + (st * 16 + 2 * q) * 4);
            float2 a1 = *(const float2*)(sbuf + (buf - sb) + BUF_DATA + (st * 16 + 8 + 2 * q) * 4);
            acc0 += ex2f(C0[0] + a0.x) + ex2f(C0[1] + a0.y)
                  + ex2f(C1[0] + a1.x) + ex2f(C1[1] + a1.y);
            acc1 += ex2f(C0[2] + a0.x) + ex2f(C0[3] + a0.y)
                  + ex2f(C1[2] + a1.x) + ex2f(C1[3] + a1.y);
        }
        __syncthreads();   // all warps done with this chunk before its buffer refills
    }

    flush(cur_pt, p0w, g, q, acc0, acc1);
}

// ===== final reduce over 16 slots per point =====
__global__ void __launch_bounds__(256)
metadyn_reduce(float* __restrict__ out)
{
    const int p = blockIdx.x * 256 + threadIdx.x;
    const float4* v = (const float4*)(g_part + p * SLOTS);
    float4 a = v[0], b = v[1], c = v[2], d = v[3];
    out[p] = (((a.x + a.y) + (a.z + a.w)) + ((b.x + b.y) + (b.z + b.w)))
           + (((c.x + c.y) + (c.z + c.w)) + ((d.x + d.y) + (d.z + d.w)));
}

extern "C" void kernel_launch(void* const* d_in, const int* in_sizes, int n_in,
                              void* d_out, int out_size)
{
    const float* col = (const float*)d_in[0];
    const float* cen = (const float*)d_in[1];
    const float* wdt = (const float*)d_in[2];
    const float* hgt = (const float*)d_in[3];
    float* out = (float*)d_out;

    pre_hills<<<N_HILLS / 512, 256>>>(cen, wdt, hgt);
    metadyn_mma<<<NCTAS, 256>>>(col);
    metadyn_reduce<<<N_POINTS / 256, 256>>>(out);
}

// round 13
// speedup vs baseline: 1.1434x; 1.0530x over previous
#include <cuda_runtime.h>
#include <cuda_bf16.h>
#include <cstdint>

// MetaDynamics via mma.sync bf16 tensor cores (compute_100-safe).
// e[p,h] = A_h + sum_{k<16} M[h,k] * X[k,p];  K=16 (8 b*x + 8 c*x^2), bias in epilogue.
//   iv = -0.5*log2e/wdt^2; b = -2*iv*cen; c = iv; A = sum iv*cen^2 + log2(hgt)
//   out[p] = sum_h 2^(e[p,h])
// bf16 hi/lo split: 3 MMAs per C tile (Xhi*Mhi + Xhi*Mlo + Xlo*Mhi), K=16 each.
// M row: 32 bf16 = 64 B: [0,8)=b hi, [8,16)=c hi, [16,24)=b lo, [24,32)=c lo.
//
// R13 = R11 validated skeleton (persistent balanced mma + 16-slot partials +
// tiny reduce kernel; measured 36.9us) with ONLY pre_hills improved:
// 1 hill/thread (128x128 grid) + __fdividef -> predicted ~2.5-3.5us (was 7.1).
// The R12 fused ticket-reduction is REVERTED (failed validation, cause not
// localizable -> removed from hot path).

#define N_HILLS   16384
#define N_POINTS  4096
#define N_CV      8

#define CHUNK     128
#define NCHUNKS   (N_HILLS / CHUNK)             // 128
#define NPTILES   (N_POINTS / 128)              // 32
#define UNITS     (NPTILES * NCHUNKS)           // 4096 (u = ptile*128 + chunk)
#define NCTAS     296
#define SLOTS     16

#define PITCH     80                            // 64B row + 16B pad (conflict-free LDSM)
#define BUF_DATA  (CHUNK * PITCH)               // 10240
#define BUF_A     (CHUNK * 4)                   // 512
#define BUF_BYTES (BUF_DATA + BUF_A)            // 10752

// ---- device-global scratch (zero-initialized at module load; unwritten slots stay 0) ----
__device__ __align__(16) __nv_bfloat16 g_M[N_HILLS * 32];       // 1 MB
__device__ __align__(16) float g_A[N_HILLS];                    // 64 KB
__device__ __align__(16) float g_part[N_POINTS * SLOTS];        // 256 KB

// ---- helpers ----
__device__ __forceinline__ uint32_t smem_u32(const void* p) {
    uint32_t a;
    asm("{ .reg .u64 t; cvta.to.shared.u64 t, %1; cvt.u32.u64 %0, t; }" : "=r"(a) : "l"(p));
    return a;
}
__device__ __forceinline__ float ex2f(float x) {
    float y; asm("ex2.approx.f32 %0, %1;" : "=f"(y) : "f"(x)); return y;
}
__device__ __forceinline__ void cp16(uint32_t dst, const void* src) {
    asm volatile("cp.async.cg.shared.global [%0], [%1], 16;" :: "r"(dst), "l"(src));
}
__device__ __forceinline__ void cp_commit() { asm volatile("cp.async.commit_group;" ::: "memory"); }
__device__ __forceinline__ void cp_wait1()  { asm volatile("cp.async.wait_group 1;" ::: "memory"); }
__device__ __forceinline__ void cp_wait0()  { asm volatile("cp.async.wait_group 0;" ::: "memory"); }

#define LDSM4(r, addr) \
    asm volatile("ldmatrix.sync.aligned.m8n8.x4.shared.b16 {%0,%1,%2,%3}, [%4];" \
        : "=r"((r)[0]), "=r"((r)[1]), "=r"((r)[2]), "=r"((r)[3]) : "r"(addr))

__device__ __forceinline__ void mma_acc(float c[4], const uint32_t a[4],
                                        uint32_t b0, uint32_t b1) {
    asm volatile(
        "mma.sync.aligned.m16n8k16.row.col.f32.bf16.bf16.f32 "
        "{%0,%1,%2,%3}, {%4,%5,%6,%7}, {%8,%9}, {%0,%1,%2,%3};"
        : "+f"(c[0]), "+f"(c[1]), "+f"(c[2]), "+f"(c[3])
        : "r"(a[0]), "r"(a[1]), "r"(a[2]), "r"(a[3]), "r"(b0), "r"(b1));
}

__device__ __forceinline__ void bf16_split(float v, __nv_bfloat16& hi, __nv_bfloat16& lo) {
    hi = __float2bfloat16_rn(v);
    lo = __float2bfloat16_rn(v - __bfloat162float(hi));
}
__device__ __forceinline__ uint32_t pack_bf(__nv_bfloat16 e0, __nv_bfloat16 e1) {
    uint32_t l = __bfloat16_as_ushort(e0), h = __bfloat16_as_ushort(e1);
    return l | (h << 16);
}

// ===== precompute: hill matrix M [16384][32] + bias A [16384]; 1 hill/thread =====
__global__ void __launch_bounds__(128)
pre_hills(const float* __restrict__ cen,
          const float* __restrict__ wdt,
          const float* __restrict__ hgt)
{
    const int h = blockIdx.x * 128 + threadIdx.x;
    const float NEG_HALF_LOG2E = -0.72134752044448170f;
    float4 c0 = *(const float4*)(cen + h * N_CV);
    float4 c1 = *(const float4*)(cen + h * N_CV + 4);
    float4 w0 = *(const float4*)(wdt + h * N_CV);
    float4 w1 = *(const float4*)(wdt + h * N_CV + 4);
    float cv[8] = {c0.x, c0.y, c0.z, c0.w, c1.x, c1.y, c1.z, c1.w};
    float wv[8] = {w0.x, w0.y, w0.z, w0.w, w1.x, w1.y, w1.z, w1.w};

    float A = log2f(hgt[h]);
    __nv_bfloat16 bh[8], bl[8], ch_[8], cl[8];
    #pragma unroll
    for (int d = 0; d < N_CV; ++d) {
        float iv = __fdividef(NEG_HALF_LOG2E, wv[d] * wv[d]);
        float b  = -2.0f * iv * cv[d];
        A = fmaf(iv * cv[d], cv[d], A);
        bf16_split(b, bh[d], bl[d]);
        bf16_split(iv, ch_[d], cl[d]);
    }
    uint4 o0, o1, o2, o3;
    o0.x = pack_bf(bh[0], bh[1]);   o0.y = pack_bf(bh[2], bh[3]);
    o0.z = pack_bf(bh[4], bh[5]);   o0.w = pack_bf(bh[6], bh[7]);
    o1.x = pack_bf(ch_[0], ch_[1]); o1.y = pack_bf(ch_[2], ch_[3]);
    o1.z = pack_bf(ch_[4], ch_[5]); o1.w = pack_bf(ch_[6], ch_[7]);
    o2.x = pack_bf(bl[0], bl[1]);   o2.y = pack_bf(bl[2], bl[3]);
    o2.z = pack_bf(bl[4], bl[5]);   o2.w = pack_bf(bl[6], bl[7]);
    o3.x = pack_bf(cl[0], cl[1]);   o3.y = pack_bf(cl[2], cl[3]);
    o3.z = pack_bf(cl[4], cl[5]);   o3.w = pack_bf(cl[6], cl[7]);
    uint4* dst = (uint4*)(g_M + h * 32);
    dst[0] = o0; dst[1] = o1; dst[2] = o2; dst[3] = o3;
    g_A[h] = A;
}

// ===== main tensor-core kernel (persistent, balanced, register-accumulated) =====
__device__ __forceinline__ void copy_chunk(uint32_t bufaddr, int hbase, int tid)
{
    const char* src = (const char*)g_M + (size_t)hbase * 64;
    #pragma unroll
    for (int k = 0; k < 2; ++k) {
        const int idx = tid + k * 256;
        const int row = idx >> 2;
        const int c   = idx & 3;
        cp16(bufaddr + row * PITCH + c * 16, src + row * 64 + c * 16);
    }
    if (tid < 32)
        cp16(bufaddr + BUF_DATA + tid * 16, (const char*)(g_A + hbase) + tid * 16);
}

__device__ __forceinline__ void build_A_frags(const float* __restrict__ col,
                                              int p0w, int g, int q,
                                              uint32_t Ahi[4], uint32_t Alo[4])
{
    const int rlo = p0w + g, rhi = rlo + 8;
    float2 xa = *(const float2*)(col + rlo * N_CV + 2 * q);
    float2 xb = *(const float2*)(col + rhi * N_CV + 2 * q);
    __nv_bfloat16 h0, l0, h1, l1;
    bf16_split(xa.x, h0, l0); bf16_split(xa.y, h1, l1);
    Ahi[0] = pack_bf(h0, h1);  Alo[0] = pack_bf(l0, l1);
    bf16_split(xb.x, h0, l0); bf16_split(xb.y, h1, l1);
    Ahi[1] = pack_bf(h0, h1);  Alo[1] = pack_bf(l0, l1);
    bf16_split(xa.x * xa.x, h0, l0); bf16_split(xa.y * xa.y, h1, l1);
    Ahi[2] = pack_bf(h0, h1);  Alo[2] = pack_bf(l0, l1);
    bf16_split(xb.x * xb.x, h0, l0); bf16_split(xb.y * xb.y, h1, l1);
    Ahi[3] = pack_bf(h0, h1);  Alo[3] = pack_bf(l0, l1);
}

__device__ __forceinline__ void flush(int pt, int p0w, int g, int q,
                                      float acc0, float acc1)
{
    // quad reduce (lanes sharing g hold disjoint hill columns)
    acc0 += __shfl_xor_sync(0xFFFFFFFFu, acc0, 1);
    acc0 += __shfl_xor_sync(0xFFFFFFFFu, acc0, 2);
    acc1 += __shfl_xor_sync(0xFFFFFFFFu, acc1, 1);
    acc1 += __shfl_xor_sync(0xFFFFFFFFu, acc1, 2);
    if (q == 0) {
        const int slot = (int)blockIdx.x - ((pt * NCTAS) >> 5);   // c_first = floor(pt*296/32)
        g_part[(p0w + g) * SLOTS + slot]     = acc0;
        g_part[(p0w + g + 8) * SLOTS + slot] = acc1;
    }
}

__global__ void __launch_bounds__(256, 2)
metadyn_mma(const float* __restrict__ col)
{
    __shared__ __align__(16) char sbuf[2 * BUF_BYTES];

    const int tid  = threadIdx.x;
    const int lane = tid & 31;
    const int warp = tid >> 5;
    const int q    = lane & 3;
    const int g    = lane >> 2;

    const int u0 = (int)(((long long)blockIdx.x * UNITS) / NCTAS);
    const int u1 = (int)(((long long)(blockIdx.x + 1) * UNITS) / NCTAS);

    const uint32_t sb = smem_u32(sbuf);
    const uint32_t lanebase = (uint32_t)(((lane & 7) | ((lane >> 4) << 3)) * PITCH
                                         + ((lane >> 3) & 1) * 16);

    int cur_pt = u0 >> 7;
    int p0w = cur_pt * 128 + warp * 16;
    uint32_t Ahi[4], Alo[4];
    build_A_frags(col, p0w, g, q, Ahi, Alo);

    copy_chunk(sb, (u0 & (NCHUNKS - 1)) * CHUNK, tid);
    cp_commit();

    float acc0 = 0.f, acc1 = 0.f;

    for (int u = u0; u < u1; ++u) {
        const uint32_t buf = sb + (uint32_t)((u - u0) & 1) * BUF_BYTES;
        if (u + 1 < u1) {
            copy_chunk(sb + (uint32_t)((u + 1 - u0) & 1) * BUF_BYTES,
                       ((u + 1) & (NCHUNKS - 1)) * CHUNK, tid);
            cp_commit();
            cp_wait1();
        } else {
            cp_wait0();
        }
        __syncthreads();

        const int pt = u >> 7;
        if (pt != cur_pt) {
            flush(cur_pt, p0w, g, q, acc0, acc1);
            acc0 = 0.f; acc1 = 0.f;
            cur_pt = pt;
            p0w = pt * 128 + warp * 16;
            build_A_frags(col, p0w, g, q, Ahi, Alo);
        }

        #pragma unroll
        for (int st = 0; st < CHUNK / 16; ++st) {      // 16 hills per step
            const uint32_t base = buf + (uint32_t)st * (16 * PITCH) + lanebase;
            uint32_t bh[4], bl[4];
            LDSM4(bh, base + 0);     // M hi: {n0 b0,b1, n1 b0,b1}
            LDSM4(bl, base + 32);    // M lo

            float C0[4] = {0.f, 0.f, 0.f, 0.f};
            float C1[4] = {0.f, 0.f, 0.f, 0.f};
            mma_acc(C0, Ahi, bh[0], bh[1]);
            mma_acc(C0, Ahi, bl[0], bl[1]);
            mma_acc(C0, Alo, bh[0], bh[1]);
            mma_acc(C1, Ahi, bh[2], bh[3]);
            mma_acc(C1, Ahi, bl[2], bl[3]);
            mma_acc(C1, Alo, bh[2], bh[3]);

            // bias (fp32) + exp2; C0 cols = hills st*16 + 2q,2q+1 ; C1 cols = +8
            float2 a0 = *(const float2*)(sbuf + (buf - sb) + BUF_DATA + (st * 16 + 2 * q) * 4);
            float2 a1 = *(const float2*)(sbuf + (buf - sb) + BUF_DATA + (st * 16 + 8 + 2 * q) * 4);
            acc0 += ex2f(C0[0] + a0.x) + ex2f(C0[1] + a0.y)
                  + ex2f(C1[0] + a1.x) + ex2f(C1[1] + a1.y);
            acc1 += ex2f(C0[2] + a0.x) + ex2f(C0[3] + a0.y)
                  + ex2f(C1[2] + a1.x) + ex2f(C1[3] + a1.y);
        }
        __syncthreads();   // all warps done with this chunk before its buffer refills
    }

    flush(cur_pt, p0w, g, q, acc0, acc1);
}

// ===== final reduce over 16 slots per point =====
__global__ void __launch_bounds__(256)
metadyn_reduce(float* __restrict__ out)
{
    const int p = blockIdx.x * 256 + threadIdx.x;
    const float4* v = (const float4*)(g_part + p * SLOTS);
    float4 a = v[0], b = v[1], c = v[2], d = v[3];
    out[p] = (((a.x + a.y) + (a.z + a.w)) + ((b.x + b.y) + (b.z + b.w)))
           + (((c.x + c.y) + (c.z + c.w)) + ((d.x + d.y) + (d.z + d.w)));
}

extern "C" void kernel_launch(void* const* d_in, const int* in_sizes, int n_in,
                              void* d_out, int out_size)
{
    const float* col = (const float*)d_in[0];
    const float* cen = (const float*)d_in[1];
    const float* wdt = (const float*)d_in[2];
    const float* hgt = (const float*)d_in[3];
    float* out = (float*)d_out;

    pre_hills<<<N_HILLS / 128, 128>>>(cen, wdt, hgt);
    metadyn_mma<<<NCTAS, 256>>>(col);
    metadyn_reduce<<<N_POINTS / 256, 256>>>(out);
}